// round 1
// baseline (speedup 1.0000x reference)
#include <cuda_runtime.h>

// Problem constants (fixed shapes per metadata):
// x: [8, 64, 32, 32] f32, W_l: [64,64], b_l: [64], W_r: [64,64]
// out: [8192, 64] f32
#define NNODES 8192
#define CDIM   64
#define KNN    9

__device__ float g_xf[NNODES * CDIM];   // flat nodes [N, C]
__device__ float g_sq[NNODES];          // row sum of squares
__device__ float g_z[NNODES * CDIM];    // x_f @ W_l^T
__device__ float g_y[NNODES * CDIM];    // x_f @ W_r^T + b_l

__device__ __forceinline__ int batch_of(int i) { return (i * 8) / 8191; }

__device__ __forceinline__ float f_inf() { return __int_as_float(0x7f800000); }

// ---------------------------------------------------------------------------
// Kernel 1: transpose [B,C,H,W] -> [N=B*H*W, C] and compute sum-of-squares.
// grid 2048 x 256 threads; each block handles 4 nodes (64 channels each).
// ---------------------------------------------------------------------------
__global__ void k_prep(const float* __restrict__ x) {
    int t = threadIdx.x;
    int n = blockIdx.x * 4 + (t >> 6);
    int c = t & 63;
    int b = n >> 10;          // / 1024
    int hw = n & 1023;
    float v = x[((b << 6) + c) * 1024 + hw];
    g_xf[n * 64 + c] = v;
    float s = v * v;
    #pragma unroll
    for (int o = 16; o; o >>= 1) s += __shfl_down_sync(0xffffffffu, s, o);
    __shared__ float part[8];
    if ((t & 31) == 0) part[t >> 5] = s;
    __syncthreads();
    if ((t & 63) == 0) g_sq[n] = part[t >> 5] + part[(t >> 5) + 1];
}

// ---------------------------------------------------------------------------
// Kernel 2: z = x_f @ W_l^T ; y = x_f @ W_r^T + b_l
// grid 128 x 128 threads; 64 nodes per block. Weights + x tile in smem.
// dynamic smem layout (bytes):
//   [0,17408)      wl[64][68]
//   [17408,34816)  wr[64][68]
//   [34816,51200)  xs[64][64]
//   [51200,51456)  bl[64]
// ---------------------------------------------------------------------------
#define G_SMEM 51456

__global__ void k_gemm(const float* __restrict__ Wl, const float* __restrict__ bl,
                       const float* __restrict__ Wr) {
    extern __shared__ char sm[];
    float (*wl)[68] = (float(*)[68])(sm);
    float (*wr)[68] = (float(*)[68])(sm + 17408);
    float (*xs)[64] = (float(*)[64])(sm + 34816);
    float* bls      = (float*)(sm + 51200);

    int t = threadIdx.x;
    int n0 = blockIdx.x * 64;

    for (int idx = t; idx < 1024; idx += 128) {           // 1024 float4s each
        int o = idx >> 4, c4 = idx & 15;
        *(float4*)&wl[o][c4 * 4] = ((const float4*)Wl)[idx];
        *(float4*)&wr[o][c4 * 4] = ((const float4*)Wr)[idx];
        *(float4*)&xs[o][c4 * 4] = ((const float4*)(g_xf + n0 * 64))[idx];
    }
    if (t < 64) bls[t] = bl[t];
    __syncthreads();

    int l = t & 31;
    int nbase = (t >> 5) * 16;
    for (int nn = 0; nn < 16; nn++) {
        int n = nbase + nn;
        float a0 = 0.f, a1 = 0.f, a2 = 0.f, a3 = 0.f;
        #pragma unroll
        for (int c4 = 0; c4 < 16; c4++) {
            float4 xv = *(float4*)&xs[n][c4 * 4];
            float4 w0 = *(float4*)&wl[l][c4 * 4];
            float4 w1 = *(float4*)&wl[l + 32][c4 * 4];
            float4 w2 = *(float4*)&wr[l][c4 * 4];
            float4 w3 = *(float4*)&wr[l + 32][c4 * 4];
            a0 += xv.x * w0.x + xv.y * w0.y + xv.z * w0.z + xv.w * w0.w;
            a1 += xv.x * w1.x + xv.y * w1.y + xv.z * w1.z + xv.w * w1.w;
            a2 += xv.x * w2.x + xv.y * w2.y + xv.z * w2.z + xv.w * w2.w;
            a3 += xv.x * w3.x + xv.y * w3.y + xv.z * w3.z + xv.w * w3.w;
        }
        int g = (n0 + n) * 64;
        g_z[g + l]      = a0;
        g_z[g + l + 32] = a1;
        g_y[g + l]      = a2 + bls[l];
        g_y[g + l + 32] = a3 + bls[l + 32];
    }
}

// ---------------------------------------------------------------------------
// Kernel 3: per-batch kNN (K=9, self included) + mean of z rows + add y.
// grid 128 x 256 threads; i-tile = 64 nodes; loop j-tiles of 64 within batch.
// Thread (ty=t/16, tx=t%16) computes a 4x4 micro-tile of dot products.
// Top-9 ownership: thread t owns i = t&63, scans j-quarter q = t>>6.
// dynamic smem layout:
//   OFF_XI   xi[64][68]   (c-major i tile)        17408
//   OFF_XJ   xj[64][68]   (c-major j tile)        17408
//   OFF_DIST dist[64][65]                         16640
//   OFF_SQI/SQJ/BI/BJ   64 each
//   OFF_CD/CI  per-thread candidate lists 256*9
//   OFF_SEL  sel[64][9], OFF_CNT scnt[64]
// ---------------------------------------------------------------------------
#define OFF_XI   0
#define OFF_XJ   17408
#define OFF_DIST 34816
#define OFF_SQI  51456
#define OFF_SQJ  51712
#define OFF_BI   51968
#define OFF_BJ   52224
#define OFF_CD   52480
#define OFF_CI   61696
#define OFF_SEL  70912
#define OFF_CNT  73216
#define K_SMEM   74240

__device__ __forceinline__ float4 f4add(float4 a, float4 b) {
    return make_float4(a.x + b.x, a.y + b.y, a.z + b.z, a.w + b.w);
}
__device__ __forceinline__ float4 f4madd(float4 a, float s, float4 b) {
    return make_float4(fmaf(a.x, s, b.x), fmaf(a.y, s, b.y),
                       fmaf(a.z, s, b.z), fmaf(a.w, s, b.w));
}

__global__ void k_knn(float* __restrict__ out) {
    extern __shared__ char sm[];
    float (*xi)[68]   = (float(*)[68])(sm + OFF_XI);
    float (*xj)[68]   = (float(*)[68])(sm + OFF_XJ);
    float (*dist)[65] = (float(*)[65])(sm + OFF_DIST);
    float* sqi = (float*)(sm + OFF_SQI);
    float* sqj = (float*)(sm + OFF_SQJ);
    int*   bi  = (int*)(sm + OFF_BI);
    int*   bj  = (int*)(sm + OFF_BJ);
    float* cd  = (float*)(sm + OFF_CD);
    int*   ci  = (int*)(sm + OFF_CI);
    int*   sel = (int*)(sm + OFF_SEL);
    int*   scnt = (int*)(sm + OFF_CNT);

    int t = threadIdx.x;
    int i0 = blockIdx.x * 64;

    // load i tile, transposed (c-major)
    for (int r = 0; r < 16; r++) {
        int idx = r * 256 + t;
        int ii = idx >> 6, cc = idx & 63;
        xi[cc][ii] = g_xf[(i0 + ii) * 64 + cc];
    }
    if (t < 64) { sqi[t] = g_sq[i0 + t]; bi[t] = batch_of(i0 + t); }

    int bfirst = batch_of(i0), blast = batch_of(i0 + 63);
    int jstart = (bfirst * 8191 + 7) >> 3;
    int jend   = ((blast + 1) * 8191 + 7) >> 3;
    if (jend > NNODES) jend = NNODES;

    float td[KNN]; int tix[KNN];
    #pragma unroll
    for (int k = 0; k < KNN; k++) { td[k] = f_inf(); tix[k] = 0x7fffffff; }

    int ty = t >> 4, tx = t & 15;
    int iown = t & 63, q = t >> 6;

    for (int j0 = jstart; j0 < jend; j0 += 64) {
        __syncthreads();   // also covers xi/sqi/bi on first iteration
        for (int r = 0; r < 16; r++) {
            int idx = r * 256 + t;
            int jj = idx >> 6, cc = idx & 63;
            int g = j0 + jj;
            xj[cc][jj] = (g < jend) ? g_xf[g * 64 + cc] : 0.f;
        }
        if (t < 64) {
            int g = j0 + t;
            sqj[t] = (g < jend) ? g_sq[g] : 0.f;
            bj[t]  = (g < jend) ? batch_of(g) : -1;
        }
        __syncthreads();

        float acc[4][4];
        #pragma unroll
        for (int p = 0; p < 4; p++)
            #pragma unroll
            for (int qq = 0; qq < 4; qq++) acc[p][qq] = 0.f;

        #pragma unroll
        for (int c = 0; c < 64; c++) {
            float4 av4 = *(float4*)&xi[c][ty * 4];
            float4 bv4 = *(float4*)&xj[c][tx * 4];
            float av[4] = {av4.x, av4.y, av4.z, av4.w};
            float bv[4] = {bv4.x, bv4.y, bv4.z, bv4.w};
            #pragma unroll
            for (int p = 0; p < 4; p++)
                #pragma unroll
                for (int qq = 0; qq < 4; qq++)
                    acc[p][qq] = fmaf(av[p], bv[qq], acc[p][qq]);
        }

        // masked distances into smem
        #pragma unroll
        for (int p = 0; p < 4; p++) {
            int il = ty * 4 + p;
            float si = sqi[il];
            int bii = bi[il];
            #pragma unroll
            for (int qq = 0; qq < 4; qq++) {
                int jl = tx * 4 + qq;
                float d = (bj[jl] == bii) ? (si + sqj[jl] - 2.0f * acc[p][qq]) : f_inf();
                dist[il][jl] = d;
            }
        }
        __syncthreads();

        // scan my quarter for my i, maintain sorted top-9 (stable: ascending j)
        #pragma unroll
        for (int k = 0; k < 16; k++) {
            int jl = q * 16 + k;
            float d = dist[iown][jl];
            if (d < td[KNN - 1]) {
                float nd = d; int ni = j0 + jl;
                #pragma unroll
                for (int s = 0; s < KNN; s++) {
                    if (nd < td[s]) {
                        float t1 = td[s]; int t2 = tix[s];
                        td[s] = nd; tix[s] = ni;
                        nd = t1; ni = t2;
                    }
                }
            }
        }
    }

    // dump per-thread candidate lists
    #pragma unroll
    for (int k = 0; k < KNN; k++) {
        cd[(iown * 4 + q) * KNN + k] = td[k];
        ci[(iown * 4 + q) * KNN + k] = tix[k];
    }
    __syncthreads();

    // 4-way merge of sorted lists per node (tie-break: lower index, matching top_k)
    if (t < 64) {
        int ptr[4] = {0, 0, 0, 0};
        int cnt = 0;
        #pragma unroll
        for (int k = 0; k < KNN; k++) {
            float bd = f_inf(); int bidx = 0x7fffffff; int bl2 = 0;
            #pragma unroll
            for (int l2 = 0; l2 < 4; l2++) {
                int o = (t * 4 + l2) * KNN + ptr[l2];
                float dd = cd[o]; int ii = ci[o];
                if (dd < bd || (dd == bd && ii < bidx)) { bd = dd; bidx = ii; bl2 = l2; }
            }
            ptr[bl2]++;
            sel[t * KNN + k] = bidx;
            if (bd < f_inf()) cnt++;
        }
        scnt[t] = cnt;
    }
    __syncthreads();

    // epilogue: out[i] = mean(z[sel]) + y[i]; 4 threads per node, 16 channels each
    int ie = t >> 2, part = t & 3;
    int gi = i0 + ie;
    float4 a0 = {0,0,0,0}, a1 = {0,0,0,0}, a2 = {0,0,0,0}, a3 = {0,0,0,0};
    int cnt = scnt[ie];
    for (int k = 0; k < cnt; k++) {
        const float4* zr = (const float4*)(g_z + sel[ie * KNN + k] * 64 + part * 16);
        a0 = f4add(a0, zr[0]);
        a1 = f4add(a1, zr[1]);
        a2 = f4add(a2, zr[2]);
        a3 = f4add(a3, zr[3]);
    }
    float inv = 1.0f / (float)cnt;
    const float4* yr = (const float4*)(g_y + gi * 64 + part * 16);
    float4* op = (float4*)(out + gi * 64 + part * 16);
    op[0] = f4madd(a0, inv, yr[0]);
    op[1] = f4madd(a1, inv, yr[1]);
    op[2] = f4madd(a2, inv, yr[2]);
    op[3] = f4madd(a3, inv, yr[3]);
}

// ---------------------------------------------------------------------------
extern "C" void kernel_launch(void* const* d_in, const int* in_sizes, int n_in,
                              void* d_out, int out_size) {
    (void)in_sizes; (void)n_in; (void)out_size;
    const float* x  = (const float*)d_in[0];
    const float* Wl = (const float*)d_in[1];
    const float* bl = (const float*)d_in[2];
    const float* Wr = (const float*)d_in[3];
    float* out = (float*)d_out;

    cudaFuncSetAttribute(k_gemm, cudaFuncAttributeMaxDynamicSharedMemorySize, G_SMEM);
    cudaFuncSetAttribute(k_knn,  cudaFuncAttributeMaxDynamicSharedMemorySize, K_SMEM);

    k_prep<<<2048, 256>>>(x);
    k_gemm<<<128, 128, G_SMEM>>>(Wl, bl, Wr);
    k_knn<<<128, 256, K_SMEM>>>(out);
}

// round 2
// speedup vs baseline: 1.9243x; 1.9243x over previous
#include <cuda_runtime.h>

// Shapes fixed: x [8,64,32,32] f32, W_l [64,64], b_l [64], W_r [64,64], out [8192,64] f32
#define NNODES 8192
#define CDIM   64
#define KNN    9

__device__ float g_xf[NNODES * CDIM];   // flat nodes [N, C]
__device__ float g_sq[NNODES];          // row sum of squares
__device__ float g_z[NNODES * CDIM];    // x_f @ W_l^T
__device__ float g_y[NNODES * CDIM];    // x_f @ W_r^T + b_l

__device__ __forceinline__ int batch_of(int i) { return (i * 8) / 8191; }
__device__ __forceinline__ float f_inf() { return __int_as_float(0x7f800000); }

// ---- packed f32x2 helpers (sm_100+) -------------------------------------
typedef unsigned long long u64t;
__device__ __forceinline__ void fma2(u64t& d, u64t a, u64t b) {
    asm("fma.rn.f32x2 %0, %1, %2, %0;" : "+l"(d) : "l"(a), "l"(b));
}
__device__ __forceinline__ float pairsum(u64t v) {
    float lo, hi;
    asm("mov.b64 {%0, %1}, %2;" : "=f"(lo), "=f"(hi) : "l"(v));
    return lo + hi;
}

// ---------------------------------------------------------------------------
// Kernel 1: coalesced transpose [B,C,H,W] -> [N,C] + row sumsq via smem tile.
// grid 128 (8 b x 16 hw-chunks) x 256 threads; tile 64 c x 64 hw.
// ---------------------------------------------------------------------------
__global__ void k_prep(const float* __restrict__ x) {
    __shared__ float s[64][65];
    int t = threadIdx.x;
    int b = blockIdx.x >> 4;
    int hw0 = (blockIdx.x & 15) << 6;
    int w = t & 63, g = t >> 6;

    #pragma unroll
    for (int r = 0; r < 16; r++) {
        int c = r * 4 + g;
        s[c][w] = x[((b << 6) + c) << 10 | (hw0 + w)];
    }
    __syncthreads();
    int base = (b << 10) + hw0;
    #pragma unroll
    for (int r = 0; r < 16; r++) {
        int nl = r * 4 + g;                     // node within tile
        g_xf[(base + nl) * 64 + w] = s[w][nl];  // w is channel here; coalesced
    }
    if (t < 64) {
        float acc = 0.f;
        #pragma unroll
        for (int c = 0; c < 64; c++) { float v = s[c][t]; acc = fmaf(v, v, acc); }
        g_sq[base + t] = acc;
    }
}

// ---------------------------------------------------------------------------
// Kernel 2: z = x_f @ W_l^T ; y = x_f @ W_r^T + b_l  (f32x2, weights hoisted)
// grid 128 x 256 threads; 64 nodes/block. smem: wl[64][68], wr[64][68], xs[64][64]
// ---------------------------------------------------------------------------
#define G_SMEM 51200

__global__ void __launch_bounds__(256, 1)
k_gemm(const float* __restrict__ Wl, const float* __restrict__ bl,
       const float* __restrict__ Wr) {
    extern __shared__ char sm[];
    float (*wl)[68] = (float(*)[68])(sm);
    float (*wr)[68] = (float(*)[68])(sm + 17408);
    float* xs       = (float*)(sm + 34816);       // [64][64] flat

    int t = threadIdx.x;
    int n0 = blockIdx.x * 64;

    #pragma unroll
    for (int r = 0; r < 4; r++) {
        int idx = r * 256 + t;
        int o = idx >> 4, c4 = idx & 15;
        *(float4*)&wl[o][c4 * 4] = ((const float4*)Wl)[idx];
        *(float4*)&wr[o][c4 * 4] = ((const float4*)Wr)[idx];
        ((float4*)xs)[idx] = ((const float4*)(g_xf + n0 * 64))[idx];
    }
    int l = t & 31;
    int ng = t >> 5;                              // node group (8 nodes)
    float bll = bl[l], blh = bl[l + 32];
    __syncthreads();

    u64t az0[8], az1[8], ay0[8], ay1[8];
    #pragma unroll
    for (int i = 0; i < 8; i++) { az0[i] = az1[i] = ay0[i] = ay1[i] = 0ull; }

    #pragma unroll
    for (int c4 = 0; c4 < 16; c4++) {
        ulonglong2 w0 = *(ulonglong2*)&wl[l][c4 * 4];
        ulonglong2 w1 = *(ulonglong2*)&wl[l + 32][c4 * 4];
        ulonglong2 w2 = *(ulonglong2*)&wr[l][c4 * 4];
        ulonglong2 w3 = *(ulonglong2*)&wr[l + 32][c4 * 4];
        #pragma unroll
        for (int nn = 0; nn < 8; nn++) {
            ulonglong2 xv = *(ulonglong2*)(xs + (ng * 8 + nn) * 64 + c4 * 4);
            fma2(az0[nn], xv.x, w0.x); fma2(az0[nn], xv.y, w0.y);
            fma2(az1[nn], xv.x, w1.x); fma2(az1[nn], xv.y, w1.y);
            fma2(ay0[nn], xv.x, w2.x); fma2(ay0[nn], xv.y, w2.y);
            fma2(ay1[nn], xv.x, w3.x); fma2(ay1[nn], xv.y, w3.y);
        }
    }
    #pragma unroll
    for (int nn = 0; nn < 8; nn++) {
        int g = (n0 + ng * 8 + nn) * 64;
        g_z[g + l]      = pairsum(az0[nn]);
        g_z[g + l + 32] = pairsum(az1[nn]);
        g_y[g + l]      = pairsum(ay0[nn]) + bll;
        g_y[g + l + 32] = pairsum(ay1[nn]) + blh;
    }
}

// ---------------------------------------------------------------------------
// Kernel 3: per-batch kNN (K=9) + mean(z[knn]) + y.
// i-tile 64, j-tile 64, 256 threads. c-paired f32x2 micro-tile 4x4.
// Tile layout: [c2][perm(float4 slot)] with even/odd float4 split so the
// 16-lane b-load is 16 consecutive float4s per LDS.128 (conflict-free).
//   word(c2, node, cc) = c2*132 + s(node>>1)*4 + (node&1)*2 + (cc&1)
//   s(f) = (f>>1) + (f&1)*16
// ---------------------------------------------------------------------------
#define OFF_XI   0          // 32*132*4 = 16896
#define OFF_XJ   16896
#define OFF_DIST 33792      // 64*68*4 = 17408
#define OFF_SQI  51200
#define OFF_SQJ  51456
#define OFF_BI   51712
#define OFF_BJ   51968
#define OFF_CD   52224      // 256*9*4
#define OFF_CI   61440
#define OFF_SEL  70656      // 64*9*4
#define OFF_CNT  72960
#define K_SMEM   73216

__device__ __forceinline__ int sw_word(int node, int cc) {
    int f = node >> 1;
    int s = (f >> 1) + ((f & 1) << 4);
    return (cc >> 1) * 132 + s * 4 + ((node & 1) << 1) + (cc & 1);
}

__device__ __forceinline__ float4 f4add(float4 a, float4 b) {
    return make_float4(a.x + b.x, a.y + b.y, a.z + b.z, a.w + b.w);
}
__device__ __forceinline__ float4 f4madd(float4 a, float s, float4 b) {
    return make_float4(fmaf(a.x, s, b.x), fmaf(a.y, s, b.y),
                       fmaf(a.z, s, b.z), fmaf(a.w, s, b.w));
}

__global__ void __launch_bounds__(256, 1)
k_knn(float* __restrict__ out) {
    extern __shared__ char sm[];
    float* xi = (float*)(sm + OFF_XI);
    float* xj = (float*)(sm + OFF_XJ);
    float* dist = (float*)(sm + OFF_DIST);    // [64][68]
    float* sqi = (float*)(sm + OFF_SQI);
    float* sqj = (float*)(sm + OFF_SQJ);
    int*   bi  = (int*)(sm + OFF_BI);
    int*   bj  = (int*)(sm + OFF_BJ);
    float* cd  = (float*)(sm + OFF_CD);
    int*   ci  = (int*)(sm + OFF_CI);
    int*   sel = (int*)(sm + OFF_SEL);
    int*   scnt = (int*)(sm + OFF_CNT);

    int t = threadIdx.x;
    int i0 = blockIdx.x * 64;
    int ty = t >> 4, tx = t & 15;
    int iown = t & 63, q = t >> 6;

    // i tile (paired-swizzled)
    #pragma unroll
    for (int r = 0; r < 16; r++) {
        int idx = r * 256 + t;
        int node = idx >> 6, cc = idx & 63;
        xi[sw_word(node, cc)] = g_xf[(i0 + node) * 64 + cc];
    }
    if (t < 64) { sqi[t] = g_sq[i0 + t]; bi[t] = batch_of(i0 + t); }

    int bfirst = batch_of(i0), blast = batch_of(i0 + 63);
    int jstart = (bfirst * 8191 + 7) >> 3;
    int jend   = ((blast + 1) * 8191 + 7) >> 3;
    if (jend > NNODES) jend = NNODES;

    float td[KNN]; int tix[KNN];
    #pragma unroll
    for (int k = 0; k < KNN; k++) { td[k] = f_inf(); tix[k] = 0x7fffffff; }

    for (int j0 = jstart; j0 < jend; j0 += 64) {
        __syncthreads();   // protects xi on iter 0; dist/xj reuse otherwise
        #pragma unroll
        for (int r = 0; r < 16; r++) {
            int idx = r * 256 + t;
            int node = idx >> 6, cc = idx & 63;
            int g = j0 + node;
            xj[sw_word(node, cc)] = (g < jend) ? g_xf[g * 64 + cc] : 0.f;
        }
        if (t < 64) {
            int g = j0 + t;
            sqj[t] = (g < jend) ? g_sq[g] : 0.f;
            bj[t]  = (g < jend) ? batch_of(g) : -1;
        }
        __syncthreads();

        u64t acc[4][4];
        #pragma unroll
        for (int p = 0; p < 4; p++)
            #pragma unroll
            for (int qq = 0; qq < 4; qq++) acc[p][qq] = 0ull;

        #pragma unroll
        for (int c2 = 0; c2 < 32; c2++) {
            const float* ri = xi + c2 * 132;
            const float* rj = xj + c2 * 132;
            ulonglong2 aLo = *(const ulonglong2*)(ri + 4 * ty);
            ulonglong2 aHi = *(const ulonglong2*)(ri + 64 + 4 * ty);
            ulonglong2 bLo = *(const ulonglong2*)(rj + 4 * tx);
            ulonglong2 bHi = *(const ulonglong2*)(rj + 64 + 4 * tx);
            u64t A[4] = {aLo.x, aLo.y, aHi.x, aHi.y};
            u64t Bv[4] = {bLo.x, bLo.y, bHi.x, bHi.y};
            #pragma unroll
            for (int p = 0; p < 4; p++)
                #pragma unroll
                for (int qq = 0; qq < 4; qq++)
                    fma2(acc[p][qq], A[p], Bv[qq]);
        }

        // masked distances -> dist smem (vectorized rows)
        #pragma unroll
        for (int p = 0; p < 4; p++) {
            int il = ty * 4 + p;
            float si = sqi[il];
            int bii = bi[il];
            float4 dr;
            float* dp = &dr.x;
            #pragma unroll
            for (int qq = 0; qq < 4; qq++) {
                int jl = tx * 4 + qq;
                float s2 = pairsum(acc[p][qq]);
                dp[qq] = (bj[jl] == bii) ? fmaf(-2.0f, s2, si + sqj[jl]) : f_inf();
            }
            *(float4*)(dist + il * 68 + tx * 4) = dr;
        }
        __syncthreads();

        // my quarter: load 16 dists, cheap min filter, then rare insertion
        const float* drow = dist + iown * 68 + q * 16;
        float4 d0 = *(const float4*)(drow + 0);
        float4 d1 = *(const float4*)(drow + 4);
        float4 d2 = *(const float4*)(drow + 8);
        float4 d3 = *(const float4*)(drow + 12);
        float m01 = fminf(fminf(d0.x, d0.y), fminf(d0.z, d0.w));
        float m23 = fminf(fminf(d1.x, d1.y), fminf(d1.z, d1.w));
        float m45 = fminf(fminf(d2.x, d2.y), fminf(d2.z, d2.w));
        float m67 = fminf(fminf(d3.x, d3.y), fminf(d3.z, d3.w));
        float mall = fminf(fminf(m01, m23), fminf(m45, m67));
        if (mall < td[KNN - 1]) {
            float dv[16] = {d0.x, d0.y, d0.z, d0.w, d1.x, d1.y, d1.z, d1.w,
                            d2.x, d2.y, d2.z, d2.w, d3.x, d3.y, d3.z, d3.w};
            #pragma unroll
            for (int k = 0; k < 16; k++) {
                float d = dv[k];
                if (d < td[KNN - 1]) {
                    float nd = d; int ni = j0 + q * 16 + k;
                    #pragma unroll
                    for (int s = 0; s < KNN; s++) {
                        if (nd < td[s]) {
                            float t1 = td[s]; int t2 = tix[s];
                            td[s] = nd; tix[s] = ni;
                            nd = t1; ni = t2;
                        }
                    }
                }
            }
        }
    }

    // dump per-thread sorted lists
    #pragma unroll
    for (int k = 0; k < KNN; k++) {
        cd[(iown * 4 + q) * KNN + k] = td[k];
        ci[(iown * 4 + q) * KNN + k] = tix[k];
    }
    __syncthreads();

    // 4-way merge per node (tie-break lower index == jax top_k stability)
    if (t < 64) {
        int ptr[4] = {0, 0, 0, 0};
        int cnt = 0;
        #pragma unroll
        for (int k = 0; k < KNN; k++) {
            float bd = f_inf(); int bidx = 0x7fffffff; int bl2 = 0;
            #pragma unroll
            for (int l2 = 0; l2 < 4; l2++) {
                int o = (t * 4 + l2) * KNN + ptr[l2];
                float dd = cd[o]; int ii = ci[o];
                if (dd < bd || (dd == bd && ii < bidx)) { bd = dd; bidx = ii; bl2 = l2; }
            }
            ptr[bl2]++;
            sel[t * KNN + k] = bidx;
            if (bd < f_inf()) cnt++;
        }
        scnt[t] = cnt;
    }
    __syncthreads();

    // epilogue: out[i] = mean(z[sel]) + y[i]; 4 threads/node x 16 channels
    int ie = t >> 2, part = t & 3;
    int gi = i0 + ie;
    float4 a0 = {0,0,0,0}, a1 = {0,0,0,0}, a2 = {0,0,0,0}, a3 = {0,0,0,0};
    int cnt = scnt[ie];
    for (int k = 0; k < cnt; k++) {
        const float4* zr = (const float4*)(g_z + sel[ie * KNN + k] * 64 + part * 16);
        a0 = f4add(a0, zr[0]);
        a1 = f4add(a1, zr[1]);
        a2 = f4add(a2, zr[2]);
        a3 = f4add(a3, zr[3]);
    }
    float inv = 1.0f / (float)cnt;
    const float4* yr = (const float4*)(g_y + gi * 64 + part * 16);
    float4* op = (float4*)(out + gi * 64 + part * 16);
    op[0] = f4madd(a0, inv, yr[0]);
    op[1] = f4madd(a1, inv, yr[1]);
    op[2] = f4madd(a2, inv, yr[2]);
    op[3] = f4madd(a3, inv, yr[3]);
}

// ---------------------------------------------------------------------------
extern "C" void kernel_launch(void* const* d_in, const int* in_sizes, int n_in,
                              void* d_out, int out_size) {
    (void)in_sizes; (void)n_in; (void)out_size;
    const float* x  = (const float*)d_in[0];
    const float* Wl = (const float*)d_in[1];
    const float* bl = (const float*)d_in[2];
    const float* Wr = (const float*)d_in[3];
    float* out = (float*)d_out;

    cudaFuncSetAttribute(k_gemm, cudaFuncAttributeMaxDynamicSharedMemorySize, G_SMEM);
    cudaFuncSetAttribute(k_knn,  cudaFuncAttributeMaxDynamicSharedMemorySize, K_SMEM);

    k_prep<<<128, 256>>>(x);
    k_gemm<<<128, 256, G_SMEM>>>(Wl, bl, Wr);
    k_knn<<<128, 256, K_SMEM>>>(out);
}

// round 5
// speedup vs baseline: 2.0211x; 1.0503x over previous
#include <cuda_runtime.h>
#include <cstdint>

// Shapes fixed: x [8,64,32,32] f32, W_l [64,64], b_l [64], W_r [64,64], out [8192,64] f32
#define NNODES 8192
#define CDIM   64
#define KNN    9
#define NTILES 128          // 64-node j/i tiles
#define TILEW  4160         // words per tile: 32 c2-rows x 128 + 64 sq
#define TILEF4 1040         // float4s per tile

__device__ float  g_xf[NNODES * CDIM];     // node-major (for k_gemm)
__device__ float4 g_xt4[NTILES * TILEF4];  // tile image: [tile][c2][slot] + sq row
__device__ float  g_z[NNODES * CDIM];      // x_f @ W_l^T
__device__ float  g_y[NNODES * CDIM];      // x_f @ W_r^T + b_l

__device__ __forceinline__ int batch_of(int i) { return (i * 8) / 8191; }
__device__ __forceinline__ float f_inf() { return __int_as_float(0x7f800000); }

typedef unsigned long long u64t;
typedef unsigned int u32t;
__device__ __forceinline__ void fma2(u64t& d, u64t a, u64t b) {
    asm("fma.rn.f32x2 %0, %1, %2, %0;" : "+l"(d) : "l"(a), "l"(b));
}
__device__ __forceinline__ float pairsum(u64t v) {
    float lo, hi;
    asm("mov.b64 {%0, %1}, %2;" : "=f"(lo), "=f"(hi) : "l"(v));
    return lo + hi;
}

__device__ __forceinline__ void cpa16(u32t sa, const void* g) {
    asm volatile("cp.async.cg.shared.global [%0], [%1], 16;" :: "r"(sa), "l"(g));
}
#define CPA_COMMIT() asm volatile("cp.async.commit_group;")
#define CPA_WAIT1()  asm volatile("cp.async.wait_group 1;" ::: "memory")

// ---------------------------------------------------------------------------
// Kernel 1: transpose + build node-major g_xf AND tile-image g_xt (+ sq row).
// grid 128 (one 64-node tile each) x 256 threads.
// Tile word layout: c2*128 + slot*4 + (nl&1)*2 + (cc&1),
//   slot(f) = (f>>1) + ((f&1)<<4), f = nl>>1. sq row at words [4096,4160).
// ---------------------------------------------------------------------------
__global__ void k_prep(const float* __restrict__ x) {
    __shared__ float s[64][65];
    int t = threadIdx.x;
    int tile = blockIdx.x;
    int b = tile >> 4;
    int hw0 = (tile & 15) << 6;
    int w = t & 63, g = t >> 6;

    #pragma unroll
    for (int r = 0; r < 16; r++) {
        int c = r * 4 + g;
        s[c][w] = x[(((b << 6) + c) << 10) | (hw0 + w)];
    }
    __syncthreads();
    int base = (b << 10) + hw0;
    #pragma unroll
    for (int r = 0; r < 16; r++) {
        int nl = r * 4 + g;
        g_xf[(base + nl) * 64 + w] = s[w][nl];
    }
    // tile image: 1024 float4s (4 per thread)
    #pragma unroll
    for (int k = 0; k < 4; k++) {
        int f4 = k * 256 + t;
        int c2 = f4 >> 5, s4 = f4 & 31;
        int f = (s4 < 16) ? (2 * s4) : (2 * (s4 - 16) + 1);
        int n0 = 2 * f, n1 = 2 * f + 1;
        int cc0 = 2 * c2, cc1 = cc0 + 1;
        float4 v = make_float4(s[cc0][n0], s[cc1][n0], s[cc0][n1], s[cc1][n1]);
        g_xt4[tile * TILEF4 + f4] = v;
    }
    if (t < 64) {
        float acc = 0.f;
        #pragma unroll
        for (int c = 0; c < 64; c++) { float v = s[c][t]; acc = fmaf(v, v, acc); }
        ((float*)g_xt4)[tile * TILEW + 4096 + t] = acc;
    }
}

// ---------------------------------------------------------------------------
// Kernel 2: z = x_f @ W_l^T ; y = x_f @ W_r^T + b_l  (f32x2, weights hoisted)
// ---------------------------------------------------------------------------
#define G_SMEM 51200

__global__ void __launch_bounds__(256, 1)
k_gemm(const float* __restrict__ Wl, const float* __restrict__ bl,
       const float* __restrict__ Wr) {
    extern __shared__ char sm[];
    float (*wl)[68] = (float(*)[68])(sm);
    float (*wr)[68] = (float(*)[68])(sm + 17408);
    float* xs       = (float*)(sm + 34816);

    int t = threadIdx.x;
    int n0 = blockIdx.x * 64;

    #pragma unroll
    for (int r = 0; r < 4; r++) {
        int idx = r * 256 + t;
        int o = idx >> 4, c4 = idx & 15;
        *(float4*)&wl[o][c4 * 4] = ((const float4*)Wl)[idx];
        *(float4*)&wr[o][c4 * 4] = ((const float4*)Wr)[idx];
        ((float4*)xs)[idx] = ((const float4*)(g_xf + n0 * 64))[idx];
    }
    int l = t & 31;
    int ng = t >> 5;
    float bll = bl[l], blh = bl[l + 32];
    __syncthreads();

    u64t az0[8], az1[8], ay0[8], ay1[8];
    #pragma unroll
    for (int i = 0; i < 8; i++) { az0[i] = az1[i] = ay0[i] = ay1[i] = 0ull; }

    #pragma unroll
    for (int c4 = 0; c4 < 16; c4++) {
        ulonglong2 w0 = *(ulonglong2*)&wl[l][c4 * 4];
        ulonglong2 w1 = *(ulonglong2*)&wl[l + 32][c4 * 4];
        ulonglong2 w2 = *(ulonglong2*)&wr[l][c4 * 4];
        ulonglong2 w3 = *(ulonglong2*)&wr[l + 32][c4 * 4];
        #pragma unroll
        for (int nn = 0; nn < 8; nn++) {
            ulonglong2 xv = *(ulonglong2*)(xs + (ng * 8 + nn) * 64 + c4 * 4);
            fma2(az0[nn], xv.x, w0.x); fma2(az0[nn], xv.y, w0.y);
            fma2(az1[nn], xv.x, w1.x); fma2(az1[nn], xv.y, w1.y);
            fma2(ay0[nn], xv.x, w2.x); fma2(ay0[nn], xv.y, w2.y);
            fma2(ay1[nn], xv.x, w3.x); fma2(ay1[nn], xv.y, w3.y);
        }
    }
    #pragma unroll
    for (int nn = 0; nn < 8; nn++) {
        int g = (n0 + ng * 8 + nn) * 64;
        g_z[g + l]      = pairsum(az0[nn]);
        g_z[g + l + 32] = pairsum(az1[nn]);
        g_y[g + l]      = pairsum(ay0[nn]) + bll;
        g_y[g + l + 32] = pairsum(ay1[nn]) + blh;
    }
}

// ---------------------------------------------------------------------------
// Kernel 3: per-batch kNN (K=9) + mean(z[knn]) + y.
// cp.async double-buffered j-tiles from the precomputed tile image.
// ---------------------------------------------------------------------------
#define OFF_XI   0           // 16640
#define OFF_XJ0  16640
#define OFF_XJ1  33280
#define OFF_DIST 49920       // [64][68]*4 = 17408
#define OFF_CD   67328       // 256*9*4
#define OFF_CI   76544
#define OFF_SEL  85760       // 64*9*4
#define OFF_CNT  88064
#define K_SMEM   88320

__device__ __forceinline__ float4 f4add(float4 a, float4 b) {
    return make_float4(a.x + b.x, a.y + b.y, a.z + b.z, a.w + b.w);
}
__device__ __forceinline__ float4 f4madd(float4 a, float s, float4 b) {
    return make_float4(fmaf(a.x, s, b.x), fmaf(a.y, s, b.y),
                       fmaf(a.z, s, b.z), fmaf(a.w, s, b.w));
}

__device__ __forceinline__ void prefetch_tile(float* dst, int tile, int t) {
    u32t sa = (u32t)__cvta_generic_to_shared(dst);
    const float4* src = g_xt4 + tile * TILEF4;
    #pragma unroll
    for (int k = 0; k < 4; k++)
        cpa16(sa + (k * 256 + t) * 16, src + k * 256 + t);
    if (t < 16)
        cpa16(sa + (1024 + t) * 16, src + 1024 + t);
}

__global__ void __launch_bounds__(256, 1)
k_knn(float* __restrict__ out) {
    extern __shared__ char sm[];
    float* xi   = (float*)(sm + OFF_XI);
    float* xjb[2] = {(float*)(sm + OFF_XJ0), (float*)(sm + OFF_XJ1)};
    float* dist = (float*)(sm + OFF_DIST);   // [64][68]
    float* cd   = (float*)(sm + OFF_CD);
    int*   ci   = (int*)(sm + OFF_CI);
    int*   sel  = (int*)(sm + OFF_SEL);
    int*   scnt = (int*)(sm + OFF_CNT);

    int t = threadIdx.x;
    int i0 = blockIdx.x * 64;
    int ty = t >> 4, tx = t & 15;
    int iown = t & 63, q = t >> 6;

    int bfirst = batch_of(i0), blast = batch_of(i0 + 63);
    int jstart = (bfirst * 8191 + 7) >> 3;
    int jend   = ((blast + 1) * 8191 + 7) >> 3;
    if (jend > NNODES) jend = NNODES;
    int jt0 = jstart >> 6;

    // prefetch first j tile, then load xi with plain vector copies
    prefetch_tile(xjb[0], jt0, t);
    CPA_COMMIT();
    {
        const float4* src = g_xt4 + blockIdx.x * TILEF4;
        float4* dst = (float4*)xi;
        #pragma unroll
        for (int k = 0; k < 4; k++) dst[k * 256 + t] = src[k * 256 + t];
        if (t < 16) dst[1024 + t] = src[1024 + t];
    }

    float siv[4]; int biv[4];
    float td[KNN]; int tix[KNN];
    #pragma unroll
    for (int k = 0; k < KNN; k++) { td[k] = f_inf(); tix[k] = 0x7fffffff; }

    int p = 0;
    bool first = true;
    for (int j0 = jstart; j0 < jend; j0 += 64) {
        int nxt = (j0 + 64) >> 6;
        if (nxt > NTILES - 1) nxt = NTILES - 1;
        prefetch_tile(xjb[p ^ 1], nxt, t);
        CPA_COMMIT();
        CPA_WAIT1();
        __syncthreads();
        const float* xj = xjb[p];

        if (first) {
            first = false;
            #pragma unroll
            for (int pp = 0; pp < 4; pp++) {
                siv[pp] = xi[4096 + ty * 4 + pp];
                biv[pp] = batch_of(i0 + ty * 4 + pp);
            }
        }

        u64t acc[4][4];
        #pragma unroll
        for (int pp = 0; pp < 4; pp++)
            #pragma unroll
            for (int qq = 0; qq < 4; qq++) acc[pp][qq] = 0ull;

        #pragma unroll 8
        for (int c2 = 0; c2 < 32; c2++) {
            const float* ri = xi + c2 * 128;
            const float* rj = xj + c2 * 128;
            ulonglong2 aLo = *(const ulonglong2*)(ri + 4 * ty);
            ulonglong2 aHi = *(const ulonglong2*)(ri + 64 + 4 * ty);
            ulonglong2 bLo = *(const ulonglong2*)(rj + 4 * tx);
            ulonglong2 bHi = *(const ulonglong2*)(rj + 64 + 4 * tx);
            u64t A[4]  = {aLo.x, aLo.y, aHi.x, aHi.y};
            u64t Bv[4] = {bLo.x, bLo.y, bHi.x, bHi.y};
            #pragma unroll
            for (int pp = 0; pp < 4; pp++)
                #pragma unroll
                for (int qq = 0; qq < 4; qq++)
                    fma2(acc[pp][qq], A[pp], Bv[qq]);
        }

        // masked distances -> dist smem
        float4 sj4 = *(const float4*)(xj + 4096 + tx * 4);
        float sjv[4] = {sj4.x, sj4.y, sj4.z, sj4.w};
        int bjv[4];
        #pragma unroll
        for (int qq = 0; qq < 4; qq++) bjv[qq] = batch_of(j0 + tx * 4 + qq);

        #pragma unroll
        for (int pp = 0; pp < 4; pp++) {
            int il = ty * 4 + pp;
            float si = siv[pp];
            int bii = biv[pp];
            float4 dr;
            float* dp = &dr.x;
            #pragma unroll
            for (int qq = 0; qq < 4; qq++) {
                float s2 = pairsum(acc[pp][qq]);
                dp[qq] = (bjv[qq] == bii) ? fmaf(-2.0f, s2, si + sjv[qq]) : f_inf();
            }
            *(float4*)(dist + il * 68 + tx * 4) = dr;
        }
        __syncthreads();

        // select on my quarter
        const float* drow = dist + iown * 68 + q * 16;
        float4 d0 = *(const float4*)(drow + 0);
        float4 d1 = *(const float4*)(drow + 4);
        float4 d2 = *(const float4*)(drow + 8);
        float4 d3 = *(const float4*)(drow + 12);
        float m01 = fminf(fminf(d0.x, d0.y), fminf(d0.z, d0.w));
        float m23 = fminf(fminf(d1.x, d1.y), fminf(d1.z, d1.w));
        float m45 = fminf(fminf(d2.x, d2.y), fminf(d2.z, d2.w));
        float m67 = fminf(fminf(d3.x, d3.y), fminf(d3.z, d3.w));
        float mall = fminf(fminf(m01, m23), fminf(m45, m67));
        if (mall < td[KNN - 1]) {
            float dv[16] = {d0.x, d0.y, d0.z, d0.w, d1.x, d1.y, d1.z, d1.w,
                            d2.x, d2.y, d2.z, d2.w, d3.x, d3.y, d3.z, d3.w};
            #pragma unroll
            for (int k = 0; k < 16; k++) {
                float d = dv[k];
                if (d < td[KNN - 1]) {
                    float nd = d; int ni = j0 + q * 16 + k;
                    #pragma unroll
                    for (int s = 0; s < KNN; s++) {
                        if (nd < td[s]) {
                            float t1 = td[s]; int t2 = tix[s];
                            td[s] = nd; tix[s] = ni;
                            nd = t1; ni = t2;
                        }
                    }
                }
            }
        }
        p ^= 1;
    }

    #pragma unroll
    for (int k = 0; k < KNN; k++) {
        cd[(iown * 4 + q) * KNN + k] = td[k];
        ci[(iown * 4 + q) * KNN + k] = tix[k];
    }
    __syncthreads();

    // 4-way merge per node (tie-break lower index == jax top_k stability)
    if (t < 64) {
        int ptr[4] = {0, 0, 0, 0};
        int cnt = 0;
        #pragma unroll
        for (int k = 0; k < KNN; k++) {
            float bd = f_inf(); int bidx = 0x7fffffff; int bl2 = 0;
            #pragma unroll
            for (int l2 = 0; l2 < 4; l2++) {
                int o = (t * 4 + l2) * KNN + ptr[l2];
                float dd = cd[o]; int ii = ci[o];
                if (dd < bd || (dd == bd && ii < bidx)) { bd = dd; bidx = ii; bl2 = l2; }
            }
            ptr[bl2]++;
            sel[t * KNN + k] = bidx;
            if (bd < f_inf()) cnt++;
        }
        scnt[t] = cnt;
    }
    __syncthreads();

    // epilogue: out[i] = mean(z[sel]) + y[i]; 4 threads/node x 16 channels
    int ie = t >> 2, part = t & 3;
    int gi = i0 + ie;
    float4 a0 = {0,0,0,0}, a1 = {0,0,0,0}, a2 = {0,0,0,0}, a3 = {0,0,0,0};
    int cnt = scnt[ie];
    for (int k = 0; k < cnt; k++) {
        const float4* zr = (const float4*)(g_z + sel[ie * KNN + k] * 64 + part * 16);
        a0 = f4add(a0, zr[0]);
        a1 = f4add(a1, zr[1]);
        a2 = f4add(a2, zr[2]);
        a3 = f4add(a3, zr[3]);
    }
    float inv = 1.0f / (float)cnt;
    const float4* yr = (const float4*)(g_y + gi * 64 + part * 16);
    float4* op = (float4*)(out + gi * 64 + part * 16);
    op[0] = f4madd(a0, inv, yr[0]);
    op[1] = f4madd(a1, inv, yr[1]);
    op[2] = f4madd(a2, inv, yr[2]);
    op[3] = f4madd(a3, inv, yr[3]);
}

// ---------------------------------------------------------------------------
extern "C" void kernel_launch(void* const* d_in, const int* in_sizes, int n_in,
                              void* d_out, int out_size) {
    (void)in_sizes; (void)n_in; (void)out_size;
    const float* x  = (const float*)d_in[0];
    const float* Wl = (const float*)d_in[1];
    const float* bl = (const float*)d_in[2];
    const float* Wr = (const float*)d_in[3];
    float* out = (float*)d_out;

    cudaFuncSetAttribute(k_gemm, cudaFuncAttributeMaxDynamicSharedMemorySize, G_SMEM);
    cudaFuncSetAttribute(k_knn,  cudaFuncAttributeMaxDynamicSharedMemorySize, K_SMEM);

    k_prep<<<128, 256>>>(x);
    k_gemm<<<128, 256, G_SMEM>>>(Wl, bl, Wr);
    k_knn<<<128, 256, K_SMEM>>>(out);
}

// round 6
// speedup vs baseline: 2.2925x; 1.1343x over previous
#include <cuda_runtime.h>
#include <cstdint>

// Shapes fixed: x [8,64,32,32] f32, W_l [64,64], b_l [64], W_r [64,64], out [8192,64] f32
#define NNODES 8192
#define CDIM   64
#define KNN    9
#define NTILES 128          // 64-node tile images
#define TILEW  4160         // words per image: 32 c2-rows x 128 + 64 sq
#define TILEF4 1040         // float4s per image

__device__ float  g_xf[NNODES * CDIM];     // node-major (for k_gemm)
__device__ float4 g_xt4[NTILES * TILEF4];  // tile images: [tile][c2][slot] + sq row
__device__ float  g_z[NNODES * CDIM];      // x_f @ W_l^T
__device__ float  g_y[NNODES * CDIM];      // x_f @ W_r^T + b_l

__device__ __forceinline__ int batch_of(int i) { return (i * 8) / 8191; }
__device__ __forceinline__ float f_inf() { return __int_as_float(0x7f800000); }

typedef unsigned long long u64t;
typedef unsigned int u32t;
__device__ __forceinline__ void fma2(u64t& d, u64t a, u64t b) {
    asm("fma.rn.f32x2 %0, %1, %2, %0;" : "+l"(d) : "l"(a), "l"(b));
}
__device__ __forceinline__ float pairsum(u64t v) {
    float lo, hi;
    asm("mov.b64 {%0, %1}, %2;" : "=f"(lo), "=f"(hi) : "l"(v));
    return lo + hi;
}
__device__ __forceinline__ void cpa16(u32t sa, const void* g) {
    asm volatile("cp.async.cg.shared.global [%0], [%1], 16;" :: "r"(sa), "l"(g));
}
#define CPA_COMMIT() asm volatile("cp.async.commit_group;")
#define CPA_WAIT1()  asm volatile("cp.async.wait_group 1;" ::: "memory")

// ---------------------------------------------------------------------------
// Kernel 1: transpose + build node-major g_xf AND tile images (+ sq row).
// Image word layout per 64-node tile: c2*128 + slot*4 + (nl&1)*2 + (cc&1),
//   slot(f) = (f>>1) + ((f&1)<<4), f = nl>>1. sq row at words [4096,4160).
// ---------------------------------------------------------------------------
__global__ void k_prep(const float* __restrict__ x) {
    __shared__ float s[64][65];
    int t = threadIdx.x;
    int tile = blockIdx.x;
    int b = tile >> 4;
    int hw0 = (tile & 15) << 6;
    int w = t & 63, g = t >> 6;

    #pragma unroll
    for (int r = 0; r < 16; r++) {
        int c = r * 4 + g;
        s[c][w] = x[(((b << 6) + c) << 10) | (hw0 + w)];
    }
    __syncthreads();
    int base = (b << 10) + hw0;
    #pragma unroll
    for (int r = 0; r < 16; r++) {
        int nl = r * 4 + g;
        g_xf[(base + nl) * 64 + w] = s[w][nl];
    }
    #pragma unroll
    for (int k = 0; k < 4; k++) {
        int f4 = k * 256 + t;
        int c2 = f4 >> 5, s4 = f4 & 31;
        int f = (s4 < 16) ? (2 * s4) : (2 * (s4 - 16) + 1);
        int n0 = 2 * f, n1 = 2 * f + 1;
        int cc0 = 2 * c2, cc1 = cc0 + 1;
        float4 v = make_float4(s[cc0][n0], s[cc1][n0], s[cc0][n1], s[cc1][n1]);
        g_xt4[tile * TILEF4 + f4] = v;
    }
    if (t < 64) {
        float acc = 0.f;
        #pragma unroll
        for (int c = 0; c < 64; c++) { float v = s[c][t]; acc = fmaf(v, v, acc); }
        ((float*)g_xt4)[tile * TILEW + 4096 + t] = acc;
    }
}

// ---------------------------------------------------------------------------
// Kernel 2: z = x_f @ W_l^T ; y = x_f @ W_r^T + b_l  (f32x2, weights hoisted)
// ---------------------------------------------------------------------------
#define G_SMEM 51200

__global__ void __launch_bounds__(256, 1)
k_gemm(const float* __restrict__ Wl, const float* __restrict__ bl,
       const float* __restrict__ Wr) {
    extern __shared__ char sm[];
    float (*wl)[68] = (float(*)[68])(sm);
    float (*wr)[68] = (float(*)[68])(sm + 17408);
    float* xs       = (float*)(sm + 34816);

    int t = threadIdx.x;
    int n0 = blockIdx.x * 64;

    #pragma unroll
    for (int r = 0; r < 4; r++) {
        int idx = r * 256 + t;
        int o = idx >> 4, c4 = idx & 15;
        *(float4*)&wl[o][c4 * 4] = ((const float4*)Wl)[idx];
        *(float4*)&wr[o][c4 * 4] = ((const float4*)Wr)[idx];
        ((float4*)xs)[idx] = ((const float4*)(g_xf + n0 * 64))[idx];
    }
    int l = t & 31;
    int ng = t >> 5;
    float bll = bl[l], blh = bl[l + 32];
    __syncthreads();

    u64t az0[8], az1[8], ay0[8], ay1[8];
    #pragma unroll
    for (int i = 0; i < 8; i++) { az0[i] = az1[i] = ay0[i] = ay1[i] = 0ull; }

    #pragma unroll
    for (int c4 = 0; c4 < 16; c4++) {
        ulonglong2 w0 = *(ulonglong2*)&wl[l][c4 * 4];
        ulonglong2 w1 = *(ulonglong2*)&wl[l + 32][c4 * 4];
        ulonglong2 w2 = *(ulonglong2*)&wr[l][c4 * 4];
        ulonglong2 w3 = *(ulonglong2*)&wr[l + 32][c4 * 4];
        #pragma unroll
        for (int nn = 0; nn < 8; nn++) {
            ulonglong2 xv = *(ulonglong2*)(xs + (ng * 8 + nn) * 64 + c4 * 4);
            fma2(az0[nn], xv.x, w0.x); fma2(az0[nn], xv.y, w0.y);
            fma2(az1[nn], xv.x, w1.x); fma2(az1[nn], xv.y, w1.y);
            fma2(ay0[nn], xv.x, w2.x); fma2(ay0[nn], xv.y, w2.y);
            fma2(ay1[nn], xv.x, w3.x); fma2(ay1[nn], xv.y, w3.y);
        }
    }
    #pragma unroll
    for (int nn = 0; nn < 8; nn++) {
        int g = (n0 + ng * 8 + nn) * 64;
        g_z[g + l]      = pairsum(az0[nn]);
        g_z[g + l + 32] = pairsum(az1[nn]);
        g_y[g + l]      = pairsum(ay0[nn]) + bll;
        g_y[g + l + 32] = pairsum(ay1[nn]) + blh;
    }
}

// ---------------------------------------------------------------------------
// Kernel 3: per-batch kNN (K=9) + mean(z[knn]) + y.
// 512 threads, i-tile 64, j-tile 128 (two images), micro-tile 8i x 2j.
// Exactly 8 j-tiles per block (batch spans 1024-aligned; batch masking
// handles node 8191). cp.async double-buffered.
// ---------------------------------------------------------------------------
#define OFF_XI   0           // 16640
#define OFF_XJ0  16640       // 33280 (two images)
#define OFF_XJ1  49920       // 33280
#define OFF_DIST 83200       // 64*132*4 = 33792
#define K_SMEM   116992
// post-loop overlays (inside dead xj region 16640..83200):
#define OFF_CD   16640       // 512*9*4 = 18432
#define OFF_CI   35072       // 18432
#define OFF_SEL  53504       // 64*9*4 = 2304
#define OFF_CNT  55808       // 256

__device__ __forceinline__ float4 f4add(float4 a, float4 b) {
    return make_float4(a.x + b.x, a.y + b.y, a.z + b.z, a.w + b.w);
}
__device__ __forceinline__ float4 f4madd(float4 a, float s, float4 b) {
    return make_float4(fmaf(a.x, s, b.x), fmaf(a.y, s, b.y),
                       fmaf(a.z, s, b.z), fmaf(a.w, s, b.w));
}

// copy two consecutive 64-node images (2080 float4) asynchronously
__device__ __forceinline__ void prefetch2(float* dst, int tile2, int t) {
    u32t sa = (u32t)__cvta_generic_to_shared(dst);
    const float4* src = g_xt4 + tile2 * TILEF4;
    #pragma unroll
    for (int k = 0; k < 4; k++)
        cpa16(sa + (k * 512 + t) * 16, src + k * 512 + t);
    if (t < 32)
        cpa16(sa + (2048 + t) * 16, src + 2048 + t);
}

__global__ void __launch_bounds__(512, 1)
k_knn(float* __restrict__ out) {
    extern __shared__ char sm[];
    float* xi   = (float*)(sm + OFF_XI);
    float* xjb[2] = {(float*)(sm + OFF_XJ0), (float*)(sm + OFF_XJ1)};
    float* dist = (float*)(sm + OFF_DIST);   // [64][132]
    float* cd   = (float*)(sm + OFF_CD);
    int*   ci   = (int*)(sm + OFF_CI);
    int*   sel  = (int*)(sm + OFF_SEL);
    int*   scnt = (int*)(sm + OFF_CNT);

    int t = threadIdx.x;
    int i0 = blockIdx.x * 64;
    int ty = t >> 6;                 // i octet 0..7
    int tx = t & 63;                 // j pair 0..63
    int iown = t & 63, q = t >> 6;   // select ownership

    // j-pair -> local node offset (invert slot permutation)
    int img = tx >> 5, sl = tx & 31;
    int fB = (sl < 16) ? (2 * sl) : (2 * (sl - 16) + 1);
    int joff0 = img * 64 + 2 * fB;   // first of this thread's 2 j-cols
    int bofsw = img * 4160 + 4 * sl; // word offset of B slot in c2-row 0
    int sqofs = img * 4160 + 4096 + 2 * fB;

    const int ioff[8] = {0, 1, 4, 5, 2, 3, 6, 7};  // A reg -> i-node offset

    int bfirst = batch_of(i0);
    int jstart = (bfirst * 8191 + 7) >> 3;   // 1024-aligned batch start
    int jt0 = jstart >> 6;                   // even image index

    prefetch2(xjb[0], jt0, t);
    CPA_COMMIT();
    {   // xi: this block's own image (1040 float4)
        const float4* src = g_xt4 + blockIdx.x * TILEF4;
        float4* dst = (float4*)xi;
        #pragma unroll
        for (int k = 0; k < 2; k++) dst[k * 512 + t] = src[k * 512 + t];
        if (t < 16) dst[1024 + t] = src[1024 + t];
    }
    __syncthreads();

    float siv[8]; int biv[8];
    #pragma unroll
    for (int a = 0; a < 8; a++) {
        int il = 8 * ty + ioff[a];
        siv[a] = xi[4096 + il];
        biv[a] = batch_of(i0 + il);
    }

    float td[KNN]; int tix[KNN];
    #pragma unroll
    for (int k = 0; k < KNN; k++) { td[k] = f_inf(); tix[k] = 0x7fffffff; }

    int p = 0;
    #pragma unroll 1
    for (int kt = 0; kt < 8; kt++) {
        int j0 = jstart + kt * 128;
        int nxt = (kt < 7) ? (jt0 + 2 * (kt + 1)) : (jt0 + 14);
        prefetch2(xjb[p ^ 1], nxt, t);
        CPA_COMMIT();
        CPA_WAIT1();
        __syncthreads();
        const float* xj = xjb[p];

        u64t acc[8][2];
        #pragma unroll
        for (int a = 0; a < 8; a++) { acc[a][0] = 0ull; acc[a][1] = 0ull; }

        const float* rb = xj + bofsw;
        const float* ra = xi + 8 * ty;
        #pragma unroll 8
        for (int c2 = 0; c2 < 32; c2++) {
            ulonglong2 B2 = *(const ulonglong2*)(rb + c2 * 128);
            ulonglong2 a0 = *(const ulonglong2*)(ra + c2 * 128);
            ulonglong2 a1 = *(const ulonglong2*)(ra + c2 * 128 + 4);
            ulonglong2 a2 = *(const ulonglong2*)(ra + c2 * 128 + 64);
            ulonglong2 a3 = *(const ulonglong2*)(ra + c2 * 128 + 68);
            u64t A[8] = {a0.x, a0.y, a1.x, a1.y, a2.x, a2.y, a3.x, a3.y};
            #pragma unroll
            for (int a = 0; a < 8; a++) {
                fma2(acc[a][0], A[a], B2.x);
                fma2(acc[a][1], A[a], B2.y);
            }
        }

        // masked distances -> dist smem
        float sj0 = xj[sqofs], sj1 = xj[sqofs + 1];
        int bj0 = batch_of(j0 + joff0);
        int bj1 = batch_of(j0 + joff0 + 1);
        #pragma unroll
        for (int a = 0; a < 8; a++) {
            int il = 8 * ty + ioff[a];
            float d0 = (bj0 == biv[a]) ? fmaf(-2.0f, pairsum(acc[a][0]), siv[a] + sj0) : f_inf();
            float d1 = (bj1 == biv[a]) ? fmaf(-2.0f, pairsum(acc[a][1]), siv[a] + sj1) : f_inf();
            *(float2*)(dist + il * 132 + joff0) = make_float2(d0, d1);
        }
        __syncthreads();

        // select on my 16-col stripe
        const float* drow = dist + iown * 132 + q * 16;
        float4 d0 = *(const float4*)(drow + 0);
        float4 d1 = *(const float4*)(drow + 4);
        float4 d2 = *(const float4*)(drow + 8);
        float4 d3 = *(const float4*)(drow + 12);
        float m01 = fminf(fminf(d0.x, d0.y), fminf(d0.z, d0.w));
        float m23 = fminf(fminf(d1.x, d1.y), fminf(d1.z, d1.w));
        float m45 = fminf(fminf(d2.x, d2.y), fminf(d2.z, d2.w));
        float m67 = fminf(fminf(d3.x, d3.y), fminf(d3.z, d3.w));
        float mall = fminf(fminf(m01, m23), fminf(m45, m67));
        if (mall < td[KNN - 1]) {
            float dv[16] = {d0.x, d0.y, d0.z, d0.w, d1.x, d1.y, d1.z, d1.w,
                            d2.x, d2.y, d2.z, d2.w, d3.x, d3.y, d3.z, d3.w};
            #pragma unroll
            for (int k = 0; k < 16; k++) {
                float d = dv[k];
                if (d < td[KNN - 1]) {
                    float nd = d; int ni = j0 + q * 16 + k;
                    #pragma unroll
                    for (int s = 0; s < KNN; s++) {
                        if (nd < td[s]) {
                            float t1 = td[s]; int t2 = tix[s];
                            td[s] = nd; tix[s] = ni;
                            nd = t1; ni = t2;
                        }
                    }
                }
            }
        }
        p ^= 1;
    }

    // dump per-thread sorted lists (overlay on dead xj region)
    #pragma unroll
    for (int k = 0; k < KNN; k++) {
        cd[(iown * 8 + q) * KNN + k] = td[k];
        ci[(iown * 8 + q) * KNN + k] = tix[k];
    }
    __syncthreads();

    // 8-way merge per node (tie-break lower index == jax top_k stability)
    if (t < 64) {
        int ptr[8] = {0, 0, 0, 0, 0, 0, 0, 0};
        int cnt = 0;
        #pragma unroll
        for (int k = 0; k < KNN; k++) {
            float bd = f_inf(); int bidx = 0x7fffffff; int bl2 = 0;
            #pragma unroll
            for (int l2 = 0; l2 < 8; l2++) {
                int o = (t * 8 + l2) * KNN + ptr[l2];
                float dd = cd[o]; int ii = ci[o];
                if (dd < bd || (dd == bd && ii < bidx)) { bd = dd; bidx = ii; bl2 = l2; }
            }
            ptr[bl2]++;
            sel[t * KNN + k] = bidx;
            if (bd < f_inf()) cnt++;
        }
        scnt[t] = cnt;
    }
    __syncthreads();

    // epilogue: out[i] = mean(z[sel]) + y[i]; 8 threads/node x 8 channels
    int ie = t >> 3, part = t & 7;
    int gi = i0 + ie;
    float4 a0 = {0,0,0,0}, a1 = {0,0,0,0};
    int cnt = scnt[ie];
    for (int k = 0; k < cnt; k++) {
        const float4* zr = (const float4*)(g_z + sel[ie * KNN + k] * 64 + part * 8);
        a0 = f4add(a0, zr[0]);
        a1 = f4add(a1, zr[1]);
    }
    float inv = 1.0f / (float)cnt;
    const float4* yr = (const float4*)(g_y + gi * 64 + part * 8);
    float4* op = (float4*)(out + gi * 64 + part * 8);
    op[0] = f4madd(a0, inv, yr[0]);
    op[1] = f4madd(a1, inv, yr[1]);
}

// ---------------------------------------------------------------------------
extern "C" void kernel_launch(void* const* d_in, const int* in_sizes, int n_in,
                              void* d_out, int out_size) {
    (void)in_sizes; (void)n_in; (void)out_size;
    const float* x  = (const float*)d_in[0];
    const float* Wl = (const float*)d_in[1];
    const float* bl = (const float*)d_in[2];
    const float* Wr = (const float*)d_in[3];
    float* out = (float*)d_out;

    cudaFuncSetAttribute(k_gemm, cudaFuncAttributeMaxDynamicSharedMemorySize, G_SMEM);
    cudaFuncSetAttribute(k_knn,  cudaFuncAttributeMaxDynamicSharedMemorySize, K_SMEM);

    k_prep<<<128, 256>>>(x);
    k_gemm<<<128, 256, G_SMEM>>>(Wl, bl, Wr);
    k_knn<<<128, 512, K_SMEM>>>(out);
}

// round 8
// speedup vs baseline: 2.8233x; 1.2315x over previous
#include <cuda_runtime.h>
#include <cuda_fp16.h>
#include <cstdint>

#define NNODES 8192
#define CDIM   64
#define KNN    9

typedef unsigned long long u64t;
typedef unsigned int u32t;

__device__ float  g_xf[NNODES * CDIM];
__device__ float4 g_sq4[NNODES / 4];
__device__ float  g_z[NNODES * CDIM];
__device__ float  g_y[NNODES * CDIM];
__device__ uint4  g_h16[NNODES * 8];
__device__ uint4  g_m16[NNODES * 8];

__device__ __forceinline__ int batch_of(int i) { return (i * 8) / 8191; }
__device__ __forceinline__ float f_ninf() { return __int_as_float(0xff800000); }

__device__ __forceinline__ void fma2(u64t& d, u64t a, u64t b) {
    asm("fma.rn.f32x2 %0, %1, %2, %0;" : "+l"(d) : "l"(a), "l"(b));
}
__device__ __forceinline__ float pairsum(u64t v) {
    float lo, hi;
    asm("mov.b64 {%0, %1}, %2;" : "=f"(lo), "=f"(hi) : "l"(v));
    return lo + hi;
}
__device__ __forceinline__ void cpa16(u32t sa, const void* g) {
    asm volatile("cp.async.cg.shared.global [%0], [%1], 16;" :: "r"(sa), "l"(g));
}
#define CPA_COMMIT() asm volatile("cp.async.commit_group;")
#define CPA_WAIT0()  asm volatile("cp.async.wait_group 0;" ::: "memory")
#define CPA_WAIT1()  asm volatile("cp.async.wait_group 1;" ::: "memory")

__device__ __forceinline__ u32t smem_u32(const void* p) {
    u32t a;
    asm("{ .reg .u64 tmp; cvta.to.shared.u64 tmp, %1; cvt.u32.u64 %0, tmp; }"
        : "=r"(a) : "l"(p));
    return a;
}
__device__ __forceinline__ void ldsm4(u32t* r, u32t addr) {
    asm volatile("ldmatrix.sync.aligned.m8n8.x4.shared.b16 {%0,%1,%2,%3}, [%4];"
        : "=r"(r[0]), "=r"(r[1]), "=r"(r[2]), "=r"(r[3]) : "r"(addr));
}
__device__ __forceinline__ void mma16816(float* c, const u32t* a, const u32t* b) {
    asm volatile("mma.sync.aligned.m16n8k16.row.col.f32.f16.f16.f32 "
        "{%0,%1,%2,%3}, {%4,%5,%6,%7}, {%8,%9}, {%0,%1,%2,%3};"
        : "+f"(c[0]), "+f"(c[1]), "+f"(c[2]), "+f"(c[3])
        : "r"(a[0]), "r"(a[1]), "r"(a[2]), "r"(a[3]), "r"(b[0]), "r"(b[1]));
}

// ---------------------------------------------------------------------------
__global__ void k_prep(const float* __restrict__ x) {
    __shared__ float s[64][65];
    int t = threadIdx.x;
    int tile = blockIdx.x;
    int b = tile >> 4;
    int hw0 = (tile & 15) << 6;
    int w = t & 63, g = t >> 6;

    #pragma unroll
    for (int r = 0; r < 16; r++) {
        int c = r * 4 + g;
        s[c][w] = x[(((b << 6) + c) << 10) | (hw0 + w)];
    }
    __syncthreads();
    int base = (b << 10) + hw0;
    #pragma unroll
    for (int r = 0; r < 16; r++) {
        int nl = r * 4 + g;
        g_xf[(base + nl) * 64 + w] = s[w][nl];
    }
    {
        int nl = t >> 2;
        int c0 = (t & 3) << 4;
        #pragma unroll
        for (int gg = 0; gg < 2; gg++) {
            u32t hw4[4], mw4[4];
            #pragma unroll
            for (int pp = 0; pp < 4; pp++) {
                float v0 = s[c0 + gg * 8 + pp * 2][nl];
                float v1 = s[c0 + gg * 8 + pp * 2 + 1][nl];
                __half h0 = __float2half_rn(v0), h1 = __float2half_rn(v1);
                float r0 = v0 - __half2float(h0), r1 = v1 - __half2float(h1);
                __half m0 = __float2half_rn(r0), m1 = __float2half_rn(r1);
                __half2 hh = __halves2half2(h0, h1);
                __half2 mm = __halves2half2(m0, m1);
                hw4[pp] = *(u32t*)&hh;
                mw4[pp] = *(u32t*)&mm;
            }
            int idx = (base + nl) * 8 + (t & 3) * 2 + gg;
            g_h16[idx] = make_uint4(hw4[0], hw4[1], hw4[2], hw4[3]);
            g_m16[idx] = make_uint4(mw4[0], mw4[1], mw4[2], mw4[3]);
        }
    }
    if (t < 64) {
        float acc = 0.f;
        #pragma unroll
        for (int c = 0; c < 64; c++) { float v = s[c][t]; acc = fmaf(v, v, acc); }
        ((float*)g_sq4)[base + t] = acc;
    }
}

// ---------------------------------------------------------------------------
#define G_SMEM 51200

__global__ void __launch_bounds__(256, 1)
k_gemm(const float* __restrict__ Wl, const float* __restrict__ bl,
       const float* __restrict__ Wr) {
    extern __shared__ char sm[];
    float (*wl)[68] = (float(*)[68])(sm);
    float (*wr)[68] = (float(*)[68])(sm + 17408);
    float* xs       = (float*)(sm + 34816);

    int t = threadIdx.x;
    int n0 = blockIdx.x * 64;

    #pragma unroll
    for (int r = 0; r < 4; r++) {
        int idx = r * 256 + t;
        int o = idx >> 4, c4 = idx & 15;
        *(float4*)&wl[o][c4 * 4] = ((const float4*)Wl)[idx];
        *(float4*)&wr[o][c4 * 4] = ((const float4*)Wr)[idx];
        ((float4*)xs)[idx] = ((const float4*)(g_xf + n0 * 64))[idx];
    }
    int l = t & 31;
    int ng = t >> 5;
    float bll = bl[l], blh = bl[l + 32];
    __syncthreads();

    u64t az0[8], az1[8], ay0[8], ay1[8];
    #pragma unroll
    for (int i = 0; i < 8; i++) { az0[i] = az1[i] = ay0[i] = ay1[i] = 0ull; }

    #pragma unroll
    for (int c4 = 0; c4 < 16; c4++) {
        ulonglong2 w0 = *(ulonglong2*)&wl[l][c4 * 4];
        ulonglong2 w1 = *(ulonglong2*)&wl[l + 32][c4 * 4];
        ulonglong2 w2 = *(ulonglong2*)&wr[l][c4 * 4];
        ulonglong2 w3 = *(ulonglong2*)&wr[l + 32][c4 * 4];
        #pragma unroll
        for (int nn = 0; nn < 8; nn++) {
            ulonglong2 xv = *(ulonglong2*)(xs + (ng * 8 + nn) * 64 + c4 * 4);
            fma2(az0[nn], xv.x, w0.x); fma2(az0[nn], xv.y, w0.y);
            fma2(az1[nn], xv.x, w1.x); fma2(az1[nn], xv.y, w1.y);
            fma2(ay0[nn], xv.x, w2.x); fma2(ay0[nn], xv.y, w2.y);
            fma2(ay1[nn], xv.x, w3.x); fma2(ay1[nn], xv.y, w3.y);
        }
    }
    #pragma unroll
    for (int nn = 0; nn < 8; nn++) {
        int g = (n0 + ng * 8 + nn) * 64;
        g_z[g + l]      = pairsum(az0[nn]);
        g_z[g + l + 32] = pairsum(az1[nn]);
        g_y[g + l]      = pairsum(ay0[nn]) + bll;
        g_y[g + l + 32] = pairsum(ay1[nn]) + blh;
    }
}

// ---------------------------------------------------------------------------
#define OFF_AH   0
#define OFF_AM   9216
#define OFF_B    18432
#define OFF_DIST 55296
#define OFF_SQJ  72704
#define OFF_SEL  76800
#define OFF_CNT  79104
#define K_SMEM   79360
#define OFF_CD   0
#define OFF_CI   9216

__device__ __forceinline__ float4 f4add(float4 a, float4 b) {
    return make_float4(a.x + b.x, a.y + b.y, a.z + b.z, a.w + b.w);
}
__device__ __forceinline__ float4 f4madd(float4 a, float s, float4 b) {
    return make_float4(fmaf(a.x, s, b.x), fmaf(a.y, s, b.y),
                       fmaf(a.z, s, b.z), fmaf(a.w, s, b.w));
}

__device__ __forceinline__ void prefetch_jtile(u32t dstbase, int jt, int t) {
    #pragma unroll
    for (int k = 0; k < 4; k++) {
        int idx = k * 256 + t;
        int sp = idx >> 9, rem = idx & 511;
        int row = rem >> 3, c = rem & 7;
        const uint4* src = (sp ? g_m16 : g_h16) + (jt * 64 + row) * 8 + c;
        cpa16(dstbase + sp * 9216 + row * 144 + c * 16, src);
    }
}

__global__ void __launch_bounds__(256, 1)
k_knn(float* __restrict__ out) {
    extern __shared__ char sm[];
    u32t sb = smem_u32(sm);
    float* dist = (float*)(sm + OFF_DIST);
    float* sqj  = (float*)(sm + OFF_SQJ);
    float* cd   = (float*)(sm + OFF_CD);
    int*   ci   = (int*)(sm + OFF_CI);
    int*   sel  = (int*)(sm + OFF_SEL);
    int*   scnt = (int*)(sm + OFF_CNT);

    int t = threadIdx.x;
    int warp = t >> 5, lane = t & 31;
    int i0 = blockIdx.x * 64;
    int b = batch_of(i0);
    int jt0 = b << 4;
    bool spc = (b == 7);

    int iown = t & 63, q = t >> 6;
    bool ib8 = (i0 + iown) == 8191;

    prefetch_jtile(sb + OFF_AH, blockIdx.x, t);
    cpa16(sb + OFF_SQJ + t * 16, g_sq4 + (b << 8) + t);
    prefetch_jtile(sb + OFF_B, jt0, t);
    CPA_COMMIT();
    prefetch_jtile(sb + OFF_B + 18432, jt0 + 1, t);
    CPA_COMMIT();
    CPA_WAIT1();
    __syncthreads();

    int m0 = (warp & 3) * 16;
    int nwin = (warp >> 2) * 32;
    u32t Ah[4][4], Am[4][4];
    {
        u32t abase = sb + (m0 + (lane & 15)) * 144 + (lane >> 4) * 16;
        #pragma unroll
        for (int k = 0; k < 4; k++) {
            ldsm4(Ah[k], abase + OFF_AH + k * 32);
            ldsm4(Am[k], abase + OFF_AM + k * 32);
        }
    }

    float wbest[KNN]; int ibest[KNN];
    #pragma unroll
    for (int k = 0; k < KNN; k++) { wbest[k] = f_ninf(); ibest[k] = 0x7fffffff; }

    u32t boff = ((lane >> 4) * 8 + (lane & 7)) * 144 + ((lane >> 3) & 1) * 16;

    #pragma unroll 1
    for (int t16 = 0; t16 < 16; t16++) {
        u32t bufb = sb + OFF_B + (t16 & 1) * 18432;
        u32t hb = bufb + nwin * 144 + boff;
        u32t mb = hb + 9216;

        float C[4][4];
        #pragma unroll
        for (int nb = 0; nb < 4; nb++)
            #pragma unroll
            for (int e = 0; e < 4; e++) C[nb][e] = 0.f;

        #pragma unroll
        for (int k = 0; k < 4; k++) {
            u32t bh[2][4], bm[2][4];
            #pragma unroll
            for (int np = 0; np < 2; np++) {
                ldsm4(bh[np], hb + np * 2304 + k * 32);
                ldsm4(bm[np], mb + np * 2304 + k * 32);
            }
            #pragma unroll
            for (int np = 0; np < 2; np++) {
                mma16816(C[np * 2 + 0], Ah[k], &bh[np][0]);
                mma16816(C[np * 2 + 1], Ah[k], &bh[np][2]);
                mma16816(C[np * 2 + 0], Am[k], &bh[np][0]);
                mma16816(C[np * 2 + 1], Am[k], &bh[np][2]);
                mma16816(C[np * 2 + 0], Ah[k], &bm[np][0]);
                mma16816(C[np * 2 + 1], Ah[k], &bm[np][2]);
            }
        }

        {
            int r0 = m0 + (lane >> 2);
            int cb = nwin + (lane & 3) * 2;
            #pragma unroll
            for (int nb = 0; nb < 4; nb++) {
                *(float2*)(dist + r0 * 68 + cb + nb * 8) = make_float2(C[nb][0], C[nb][1]);
                *(float2*)(dist + (r0 + 8) * 68 + cb + nb * 8) = make_float2(C[nb][2], C[nb][3]);
            }
        }
        __syncthreads();

        if (t16 < 14) {
            prefetch_jtile(sb + OFF_B + (t16 & 1) * 18432, jt0 + t16 + 2, t);
            CPA_COMMIT();
            CPA_WAIT1();
        } else {
            CPA_WAIT0();
        }

        {
            const float* drow = dist + iown * 68 + q * 16;
            const float* srow = sqj + t16 * 64 + q * 16;
            float4 d0 = *(const float4*)(drow + 0);
            float4 d1 = *(const float4*)(drow + 4);
            float4 d2 = *(const float4*)(drow + 8);
            float4 d3 = *(const float4*)(drow + 12);
            float4 s0 = *(const float4*)(srow + 0);
            float4 s1 = *(const float4*)(srow + 4);
            float4 s2 = *(const float4*)(srow + 8);
            float4 s3 = *(const float4*)(srow + 12);
            float4 w0 = make_float4(fmaf(2.f, d0.x, -s0.x), fmaf(2.f, d0.y, -s0.y),
                                    fmaf(2.f, d0.z, -s0.z), fmaf(2.f, d0.w, -s0.w));
            float4 w1 = make_float4(fmaf(2.f, d1.x, -s1.x), fmaf(2.f, d1.y, -s1.y),
                                    fmaf(2.f, d1.z, -s1.z), fmaf(2.f, d1.w, -s1.w));
            float4 w2 = make_float4(fmaf(2.f, d2.x, -s2.x), fmaf(2.f, d2.y, -s2.y),
                                    fmaf(2.f, d2.z, -s2.z), fmaf(2.f, d2.w, -s2.w));
            float4 w3 = make_float4(fmaf(2.f, d3.x, -s3.x), fmaf(2.f, d3.y, -s3.y),
                                    fmaf(2.f, d3.z, -s3.z), fmaf(2.f, d3.w, -s3.w));
            if (spc) {
                bool last = (t16 == 15) && (q == 3);
                if (ib8) {
                    float keep = last ? w3.w : f_ninf();
                    float ni = f_ninf();
                    w0 = make_float4(ni, ni, ni, ni);
                    w1 = w0; w2 = w0;
                    w3 = make_float4(ni, ni, ni, keep);
                } else if (last) {
                    w3.w = f_ninf();
                }
            }
            float m01 = fmaxf(fmaxf(w0.x, w0.y), fmaxf(w0.z, w0.w));
            float m23 = fmaxf(fmaxf(w1.x, w1.y), fmaxf(w1.z, w1.w));
            float m45 = fmaxf(fmaxf(w2.x, w2.y), fmaxf(w2.z, w2.w));
            float m67 = fmaxf(fmaxf(w3.x, w3.y), fmaxf(w3.z, w3.w));
            float mall = fmaxf(fmaxf(m01, m23), fmaxf(m45, m67));
            if (mall > wbest[KNN - 1]) {
                int j0 = (b << 10) + t16 * 64 + q * 16;
                float wv[16] = {w0.x, w0.y, w0.z, w0.w, w1.x, w1.y, w1.z, w1.w,
                                w2.x, w2.y, w2.z, w2.w, w3.x, w3.y, w3.z, w3.w};
                #pragma unroll
                for (int k = 0; k < 16; k++) {
                    float d = wv[k];
                    if (d > wbest[KNN - 1]) {
                        float nw = d; int ni = j0 + k;
                        #pragma unroll
                        for (int s = 0; s < KNN; s++) {
                            if (nw > wbest[s]) {
                                float t1 = wbest[s]; int t2 = ibest[s];
                                wbest[s] = nw; ibest[s] = ni;
                                nw = t1; ni = t2;
                            }
                        }
                    }
                }
            }
        }
        __syncthreads();
    }

    #pragma unroll
    for (int k = 0; k < KNN; k++) {
        cd[(iown * 4 + q) * KNN + k] = wbest[k];
        ci[(iown * 4 + q) * KNN + k] = ibest[k];
    }
    __syncthreads();

    if (t < 64) {
        int ptr[4] = {0, 0, 0, 0};
        int cnt = 0;
        #pragma unroll
        for (int k = 0; k < KNN; k++) {
            float bw = f_ninf(); int bidx = 0x7fffffff; int bl2 = 0;
            #pragma unroll
            for (int l2 = 0; l2 < 4; l2++) {
                int o = (t * 4 + l2) * KNN + ptr[l2];
                float wd = cd[o]; int ii = ci[o];
                if (wd > bw || (wd == bw && ii < bidx)) { bw = wd; bidx = ii; bl2 = l2; }
            }
            ptr[bl2]++;
            sel[t * KNN + k] = bidx;
            if (bw > f_ninf()) cnt++;
        }
        if (cnt == 0) { sel[t * KNN] = i0 + t; cnt = 1; }
        scnt[t] = cnt;
    }
    __syncthreads();

    int ie = t >> 2, part = t & 3;
    int gi = i0 + ie;
    float4 a0 = {0,0,0,0}, a1 = {0,0,0,0}, a2 = {0,0,0,0}, a3 = {0,0,0,0};
    int cnt = scnt[ie];
    for (int k = 0; k < cnt; k++) {
        const float4* zr = (const float4*)(g_z + sel[ie * KNN + k] * 64 + part * 16);
        a0 = f4add(a0, zr[0]);
        a1 = f4add(a1, zr[1]);
        a2 = f4add(a2, zr[2]);
        a3 = f4add(a3, zr[3]);
    }
    float inv = 1.0f / (float)cnt;
    const float4* yr = (const float4*)(g_y + gi * 64 + part * 16);
    float4* op = (float4*)(out + gi * 64 + part * 16);
    op[0] = f4madd(a0, inv, yr[0]);
    op[1] = f4madd(a1, inv, yr[1]);
    op[2] = f4madd(a2, inv, yr[2]);
    op[3] = f4madd(a3, inv, yr[3]);
}

// ---------------------------------------------------------------------------
extern "C" void kernel_launch(void* const* d_in, const int* in_sizes, int n_in,
                              void* d_out, int out_size) {
    (void)in_sizes; (void)n_in; (void)out_size;
    const float* x  = (const float*)d_in[0];
    const float* Wl = (const float*)d_in[1];
    const float* bl = (const float*)d_in[2];
    const float* Wr = (const float*)d_in[3];
    float* out = (float*)d_out;

    cudaFuncSetAttribute(k_gemm, cudaFuncAttributeMaxDynamicSharedMemorySize, G_SMEM);
    cudaFuncSetAttribute(k_knn,  cudaFuncAttributeMaxDynamicSharedMemorySize, K_SMEM);

    k_prep<<<128, 256>>>(x);
    k_gemm<<<128, 256, G_SMEM>>>(Wl, bl, Wr);
    k_knn<<<128, 256, K_SMEM>>>(out);
}